// round 11
// baseline (speedup 1.0000x reference)
#include <cuda_runtime.h>

// Shapes fixed by the dataset: u (B=64, L=8192), ev (K=32, L), lam (K)
#define L      8192
#define NB     64
#define NK     32
#define HALF   4096   // L/2
#define KD     2048   // number of odd d < L/2
#define NBLK   128    // grid size (all co-resident: 1 block/SM, 128 <= 148)

typedef unsigned long long u64;

// Device scratch (no allocs allowed)
__device__ __align__(16) float g_ct2 [KD + 8];  // (2/L)*cot(pi*(2k+1)/L), padded
__device__ __align__(16) float g_ct2s[KD + 8];  // shifted copy: g_ct2s[i] = g_ct2[i+1]
__device__ float g_P[L];      // P[l] = sum_k lam_k ev[k][l]
__device__ float g_Po[HALF];  // P at odd l
__device__ float g_Pe[HALF];  // P at even l
__device__ float g_a[NB];     // Re(sum_i rfft(u)[b,i])
__device__ float g_c[NB];     // Im(sum_i rfft(u)[b,i])
__device__ int   g_cnt;       // grid-barrier epoch counter

// packed f32x2 FMA: d.lo += a.lo*b.lo; d.hi += a.hi*b.hi
__device__ __forceinline__ void fma2(u64& d, u64 a, u64 b) {
    asm("fma.rn.f32x2 %0, %1, %2, %0;" : "+l"(d) : "l"(a), "l"(b));
}
__device__ __forceinline__ float hadd2(u64 v) {
    float lo, hi;
    asm("mov.b64 {%0,%1}, %2;" : "=f"(lo), "=f"(hi) : "l"(v));
    return lo + hi;
}

// ---------------------------------------------------------------------------
// Fused persistent kernel: 128 blocks x 1024 threads, all resident.
__global__ void __launch_bounds__(1024, 1) kfused(const float* __restrict__ u,
                                                  const float* __restrict__ ev,
                                                  const float* __restrict__ lam,
                                                  float* __restrict__ out) {
    __shared__ alignas(16) float SA [2112];
    __shared__ alignas(16) float SRa[2112];   // reversed B operand
    __shared__ alignas(16) float red2[32 * 68];
    __shared__ float Ps[64], aS[NB], cS[NB], Qs[64];
    __shared__ float wa[32], wc[32];

    const int t  = threadIdx.x;
    const int bx = blockIdx.x;

    // ======================= Phase 1 =======================
    if (bx < NB) {
        // ---- a/c reduction for batch b = bx ----
        const float4* u4 = (const float4*)(u + (size_t)bx * L);
        float a = 0.0f, c = 0.0f;
#pragma unroll
        for (int r = 0; r < 2; r++) {
            int i = r * 1024 + t;                 // float4 index, 2048 per row
            float4 uv = u4[i];
            float x1 = (float)(4 * i + 1) * (1.0f / (float)L);
            float x3 = (float)(4 * i + 3) * (1.0f / (float)L);
            float c1 = __fdividef(cospif(x1), sinpif(x1));
            float c3 = __fdividef(cospif(x3), sinpif(x3));
            a += uv.x + uv.z;
            c -= uv.y * c1 + uv.w * c3;
            if (i == 0) a += (float)(L / 2) * uv.x;
        }
#pragma unroll
        for (int off = 16; off > 0; off >>= 1) {
            a += __shfl_down_sync(0xffffffffu, a, off);
            c += __shfl_down_sync(0xffffffffu, c, off);
        }
        const int lane = t & 31, w = t >> 5;
        if (lane == 0) { wa[w] = a; wc[w] = c; }
        __syncthreads();
        if (t < 32) {
            float av = wa[t], cv = wc[t];
#pragma unroll
            for (int off = 16; off > 0; off >>= 1) {
                av += __shfl_down_sync(0xffffffffu, av, off);
                cv += __shfl_down_sync(0xffffffffu, cv, off);
            }
            if (t == 0) { g_a[bx] = av; g_c[bx] = cv; }
        }
    } else {
        // ---- P chunk + cot tables ----
        const int pb = bx - NB;             // 0..63
        const int l4 = pb * 32 + (t >> 5);  // float4-of-l index (0..2047)
        const int k  = t & 31;              // eigenvector row
        float4 e  = ((const float4*)ev)[k * (L / 4) + l4];
        float  lk = __ldg(lam + k);
        float4 v; v.x = lk * e.x; v.y = lk * e.y; v.z = lk * e.z; v.w = lk * e.w;
#pragma unroll
        for (int off = 16; off > 0; off >>= 1) {
            v.x += __shfl_down_sync(0xffffffffu, v.x, off);
            v.y += __shfl_down_sync(0xffffffffu, v.y, off);
            v.z += __shfl_down_sync(0xffffffffu, v.z, off);
            v.w += __shfl_down_sync(0xffffffffu, v.w, off);
        }
        if (k == 0) {
            ((float4*)g_P)[l4] = v;
            g_Pe[2 * l4]     = v.x;  g_Po[2 * l4]     = v.y;
            g_Pe[2 * l4 + 1] = v.z;  g_Po[2 * l4 + 1] = v.w;
        }
        if (t < 32) {
            int idx = pb * 32 + t;          // 0..2047
            float x = (float)(2 * idx + 1) * (1.0f / (float)L);
            float val = (2.0f / (float)L) * __fdividef(cospif(x), sinpif(x));
            g_ct2[idx] = val;
            if (idx > 0) g_ct2s[idx - 1] = val;
            if (idx == 0) {                 // zero the pads (only once per grid)
                if (pb == 0) {
#pragma unroll
                    for (int z = 0; z < 8; z++) {
                        g_ct2 [KD + z] = 0.0f;
                        g_ct2s[KD - 1 + z] = 0.0f;
                    }
                }
            }
        }
        __syncthreads();   // keep phase-1 barrier count identical on all paths
    }

    // ======================= Grid barrier =======================
    __threadfence();                        // publish phase-1 writes (L2)
    if (t == 0) {
        int old = atomicAdd(&g_cnt, 1);
        int target = ((old >> 7) + 1) << 7; // round old+1 up to multiple of 128
        while (*(volatile int*)&g_cnt < target) __nanosleep(64);
    }
    __syncthreads();

    // ======================= Phase 2 =======================
    // Block bx: p = bx>>6 (parity), m0 = (bx&63)*64 — 64 l's: l = 2*(m0+mm)+p.
    // Q[l] = sum_{kk=0}^{2047} ct2[kk]*(A - B),
    //   A(m,kk) = S[(m+kk+p)&4095],  B(m,kk) = S[(m-kk-1+p)&4095].
    // SA[x]  = S[(m0+p+x)&4095]      -> alpha[i] = SA[4ly+32j + i], i = kk+r
    // SRa[x] = S[(m0+p+63-x)&4095]   -> beta[i]  = SRa[32j-4ly+64 + i], i = kk-r
    // Packed over kk: even-r uses natural C pairs (g_ct2), odd-r uses the
    // shifted table (g_ct2s) pairs + 2 boundary scalars. All operand pairs
    // are natural b64 halves of 16B loads — zero packing movs.
    const int p  = bx >> 6;
    const int m0 = (bx & 63) * 64;

    {
        const float* S = p ? g_Pe : g_Po;
        const int baseA = m0 + p;
        const int baseR = m0 + p + 63 + 2 * HALF;   // keep positive before mask
#pragma unroll
        for (int x = t; x < 2112; x += 1024) {
            SA [x] = S[(baseA + x) & (HALF - 1)];
            SRa[x] = S[(baseR - x) & (HALF - 1)];
        }
    }
    if (t < NB) {
        aS[t] = g_a[t]; cS[t] = g_c[t];
    } else if (t < NB + 64) {
        int mm = t - NB;
        Ps[mm] = g_P[2 * (m0 + mm) + p];
    }
    __syncthreads();

    const int ly = t & 15;              // m = m0 + 4*ly + r
    const int j  = t >> 4;              // 0..63, kk-chunk [32j, 32j+32)
    const int xa  = 4 * ly + 32 * j;    // float base in SA  (mult of 4)
    const int xb  = 32 * j - 4 * ly + 64;  // float base in SRa (mult of 4)
    const int xa4 = xa >> 2;
    const int xb4 = xb >> 2;

    const ulonglong2* SA2 = (const ulonglong2*)SA;
    const ulonglong2* SB2 = (const ulonglong2*)SRa;
    const ulonglong2* CN2 = (const ulonglong2*)g_ct2;
    const ulonglong2* CS2 = (const ulonglong2*)g_ct2s;

    u64 p0 = 0, p1 = 0, p2 = 0, p3 = 0;
    u64 n0 = 0, n1 = 0, n2 = 0, n3 = 0;

    ulonglong2 A0  = SA2[xa4];          // alpha[0..3]
    u64        bph = SB2[xb4 - 1].y;    // beta[-2], beta[-1]

#pragma unroll
    for (int it = 0; it < 8; it++) {
        ulonglong2 A1 = SA2[xa4 + it + 1];   // alpha[4it+4 .. 4it+7]
        ulonglong2 Bc = SB2[xb4 + it];       // beta [4it   .. 4it+3]
        ulonglong2 Cn = CN2[8 * j + it];     // (c0,c1),(c2,c3) of this 4-chunk
        ulonglong2 Cs = CS2[8 * j + it];     // (c1,c2),(c3,c4)
        // even r
        fma2(p0, Cn.x, A0.x);  fma2(p0, Cn.y, A0.y);
        fma2(p2, Cn.x, A0.y);  fma2(p2, Cn.y, A1.x);
        fma2(n0, Cn.x, Bc.x);  fma2(n0, Cn.y, Bc.y);
        fma2(n2, Cn.x, bph);   fma2(n2, Cn.y, Bc.x);
        // odd r (u = 2it)
        fma2(p1, Cs.x, A0.y);
        fma2(p3, Cs.x, A1.x);
        fma2(n1, Cs.x, Bc.x);
        fma2(n3, Cs.x, bph);
        if (it < 7) {           // odd r (u = 2it+1); u=15 is the excluded pair
            fma2(p1, Cs.y, A1.x);
            fma2(p3, Cs.y, A1.y);
            fma2(n1, Cs.y, Bc.y);
            fma2(n3, Cs.y, Bc.x);
        }
        A0 = A1; bph = Bc.y;    // rolling windows (both advance +4 floats)
    }

    // Boundary scalars for odd r: kk=0 and kk=31 terms.
    const float c0  = g_ct2[32 * j];
    const float c31 = g_ct2[32 * j + 31];
    float acc0 = hadd2(p0) - hadd2(n0);
    float acc2 = hadd2(p2) - hadd2(n2);
    float acc1 = (hadd2(p1) - hadd2(n1))
               + c0  * (SA[xa + 1]  - SRa[xb - 1])
               + c31 * (SA[xa + 32] - SRa[xb + 30]);
    float acc3 = (hadd2(p3) - hadd2(n3))
               + c0  * (SA[xa + 3]  - SRa[xb - 3])
               + c31 * (SA[xa + 34] - SRa[xb + 28]);

    // Lanes 0-15 of each warp absorb lanes 16-31 (same ly, j+1).
    acc0 += __shfl_down_sync(0xffffffffu, acc0, 16);
    acc1 += __shfl_down_sync(0xffffffffu, acc1, 16);
    acc2 += __shfl_down_sync(0xffffffffu, acc2, 16);
    acc3 += __shfl_down_sync(0xffffffffu, acc3, 16);

    const int lane = t & 31, w = t >> 5;
    if (lane < 16) {
        float4 v; v.x = acc0; v.y = acc1; v.z = acc2; v.w = acc3;
        ((float4*)(red2 + w * 68))[lane] = v;     // red2[w*68 + 4*ly + r]
    }
    __syncthreads();

    if (t < 64) {
        float s = 0.0f;
#pragma unroll
        for (int w2 = 0; w2 < 32; w2++) s += red2[w2 * 68 + t];
        Qs[t] = s;                       // ct2 already carries 2/L
    }
    __syncthreads();

    // 64 b x 64 m outputs, 4 per thread
#pragma unroll
    for (int r = 0; r < 4; r++) {
        int idx = r * 1024 + t;
        int b   = idx >> 6;
        int mm  = idx & 63;
        out[(size_t)b * L + 2 * (m0 + mm) + p] =
            fmaf(aS[b], Ps[mm], cS[b] * Qs[mm]);
    }
}

// ---------------------------------------------------------------------------
extern "C" void kernel_launch(void* const* d_in, const int* in_sizes, int n_in,
                              void* d_out, int out_size) {
    const float* u   = (const float*)d_in[0];  // (64, 8192)
    const float* ev  = (const float*)d_in[1];  // (32, 8192)
    const float* lam = (const float*)d_in[2];  // (32,)
    float* out = (float*)d_out;                // (64, 8192)

    kfused<<<NBLK, 1024>>>(u, ev, lam, out);
}

// round 12
// speedup vs baseline: 1.1946x; 1.1946x over previous
#include <cuda_runtime.h>

// Shapes fixed by the dataset: u (B=64, L=8192), ev (K=32, L), lam (K)
#define L      8192
#define NB     64
#define NK     32
#define HALF   4096   // L/2
#define KD     2048   // number of odd d < L/2
#define NBLK   128    // grid size (all co-resident: 1 block/SM, 128 <= 148)

// Device scratch (no allocs allowed)
__device__ float g_ct2[KD];    // (2/L)*cot(pi*(2k+1)/L)
__device__ float g_P[L];       // P[l] = sum_k lam_k ev[k][l]
__device__ float g_Po[HALF];   // P at odd l
__device__ float g_Pe[HALF];   // P at even l
__device__ float g_pa2[NBLK];  // half-row Re partials
__device__ float g_pc2[NBLK];  // half-row Im partials
__device__ int   g_cnt;        // grid-barrier epoch counter

// ---------------------------------------------------------------------------
// Fused persistent kernel: 128 blocks x 1024 threads, all resident.
// Phase 1 (every block, balanced):
//   a/c: block bx -> batch b = bx>>1, half = bx&1; one float4 of u per thread,
//        warp+block reduce -> g_pa2[bx], g_pc2[bx].
//   P:   block bx -> l in [bx*64, bx*64+64). Threads 0..511: (k = t>>4,
//        lo = t&15) load ev4[k*2048 + bx*16 + lo] (coalesced 256B runs),
//        scale by lam[k], park in smem; threads 0..63 reduce over k and write
//        g_P + parity copies. Threads 0..15 fill ct2 chunk.
// Grid barrier, then Phase 2 (identical to the best-measured R10 kernel).
__global__ void __launch_bounds__(1024, 1) kfused(const float* __restrict__ u,
                                                  const float* __restrict__ ev,
                                                  const float* __restrict__ lam,
                                                  float* __restrict__ out) {
    __shared__ alignas(16) float SA[2112];
    __shared__ alignas(16) float SB[2120];
    __shared__ alignas(16) float red2[32 * 68];   // also reused as PS in phase 1
    __shared__ float Ps[64], aS[NB], cS[NB], Qs[64];
    __shared__ float wa[32], wc[32];

    const int t  = threadIdx.x;
    const int bx = blockIdx.x;

    // ======================= Phase 1 =======================
    {
        float* PS = red2;                    // 32 x 64 floats (k-major partials)

        // -- issue both global loads early (independent DRAM streams) --
        const int b    = bx >> 1;
        const int half = bx & 1;
        const int i    = half * 1024 + t;    // float4 index in u row (2048/row)
        float4 uv = ((const float4*)(u + (size_t)b * L))[i];

        float4 e4;
        const int k  = t >> 4;               // 0..63 but only t<512 used (k<32)
        const int lo = t & 15;
        if (t < 512)
            e4 = ((const float4*)ev)[k * (L / 4) + bx * 16 + lo];

        // -- a/c partial --
        float x1 = (float)(4 * i + 1) * (1.0f / (float)L);
        float x3 = (float)(4 * i + 3) * (1.0f / (float)L);
        float c1 = __fdividef(cospif(x1), sinpif(x1));
        float c3 = __fdividef(cospif(x3), sinpif(x3));
        float a = uv.x + uv.z;
        float c = -(uv.y * c1 + uv.w * c3);
        if (i == 0) a += (float)(L / 2) * uv.x;
#pragma unroll
        for (int off = 16; off > 0; off >>= 1) {
            a += __shfl_down_sync(0xffffffffu, a, off);
            c += __shfl_down_sync(0xffffffffu, c, off);
        }
        const int lane = t & 31, w = t >> 5;
        if (lane == 0) { wa[w] = a; wc[w] = c; }

        // -- P partial: park lam[k]*ev in smem --
        if (t < 512) {
            float lk = __ldg(lam + k);
            float4 v; v.x = lk * e4.x; v.y = lk * e4.y; v.z = lk * e4.z; v.w = lk * e4.w;
            ((float4*)PS)[k * 16 + lo] = v;  // PS[k*64 + 4*lo + comp]
        }
        __syncthreads();

        // -- P reduce: thread q < 64 sums over k, writes l = bx*64 + q --
        if (t < 64) {
            float s = 0.0f;
#pragma unroll
            for (int kk = 0; kk < NK; kk++) s += PS[kk * 64 + t];
            const int l = bx * 64 + t;
            g_P[l] = s;
            if (l & 1) g_Po[l >> 1] = s; else g_Pe[l >> 1] = s;
        } else if (t < 96) {
            // -- a/c final reduce (warp 2, lanes = t-64) --
            float av = wa[t - 64], cv = wc[t - 64];
#pragma unroll
            for (int off = 16; off > 0; off >>= 1) {
                av += __shfl_down_sync(0xffffffffu, av, off);
                cv += __shfl_down_sync(0xffffffffu, cv, off);
            }
            if (t == 64) { g_pa2[bx] = av; g_pc2[bx] = cv; }
        } else if (t < 112) {
            // -- ct2 chunk: idx in [bx*16, bx*16+16) --
            int idx = bx * 16 + (t - 96);
            float x = (float)(2 * idx + 1) * (1.0f / (float)L);
            g_ct2[idx] = (2.0f / (float)L) * __fdividef(cospif(x), sinpif(x));
        }
        __syncthreads();   // red2 reused in phase 2
    }

    // ======================= Grid barrier =======================
    __threadfence();                        // publish phase-1 writes
    if (t == 0) {
        int old = atomicAdd(&g_cnt, 1);
        int target = ((old >> 7) + 1) << 7; // round old+1 up to multiple of 128
        while (*(volatile int*)&g_cnt < target) __nanosleep(64);
    }
    __syncthreads();

    // ======================= Phase 2 (R10, best measured) =======================
    const int p  = bx >> 6;
    const int m0 = (bx & 63) * 64;

    // Stage shifted copies of the opposite-parity half of P:
    //   A(m,k) = S[m+k+p]    -> SA[x] = S[(m0+p+x) & 4095],       A = SA[mm+k]
    //   B(m,k) = S[m-k-1+p]  -> SB[y] = S[(m0+p-2052+y) & 4095],  B = SB[mm-k+2051]
    {
        const float* S = p ? g_Pe : g_Po;
        const int baseA = m0 + p;
        const int baseB = m0 + p - 2052 + HALF;   // keep positive before mask
#pragma unroll
        for (int x = t; x < 2112; x += 1024) SA[x] = S[(baseA + x) & (HALF - 1)];
#pragma unroll
        for (int y = t; y < 2120; y += 1024) SB[y] = S[(baseB + y) & (HALF - 1)];
    }
    if (t < NB) {
        aS[t] = g_pa2[2 * t] + g_pa2[2 * t + 1];
        cS[t] = g_pc2[2 * t] + g_pc2[2 * t + 1];
    } else if (t < NB + 64) {
        int mm = t - NB;
        Ps[mm] = g_P[2 * (m0 + mm) + p];
    }
    __syncthreads();

    const int ly = t & 15;              // m-subtile: m = m0 + 4*ly + r
    const int j  = t >> 4;              // 0..63, k-range [32j, 32j+32)
    const float4* SA4 = (const float4*)SA;
    const float4* SB4 = (const float4*)SB;
    const float4* CT4 = (const float4*)g_ct2;

    const int xa0 = ly + 8 * j;         // A float4 base at kt=0
    const int xb0 = 512 + ly - 8 * j;   // B low float4 base at kt=0

    float4 A0 = SA4[xa0];               // a0..a3 for current kt
    float4 B1 = SB4[xb0 + 1];           // b4..b7 for current kt

    float p0 = 0.f, p1 = 0.f, p2 = 0.f, p3 = 0.f;   // + accumulators (C*a)
    float n0 = 0.f, n1 = 0.f, n2 = 0.f, n3 = 0.f;   // - accumulators (C*b)
#pragma unroll
    for (int kt = 0; kt < 8; kt++) {
        float4 A1 = SA4[xa0 + kt + 1];  // a4..a7
        float4 B0 = SB4[xb0 - kt];      // b0..b3
        float4 C  = __ldg(&CT4[8 * j + kt]);
        float a0 = A0.x, a1 = A0.y, a2 = A0.z, a3 = A0.w;
        float a4 = A1.x, a5 = A1.y, a6 = A1.z;
        float b0 = B0.x, b1 = B0.y, b2 = B0.z, b3 = B0.w;
        float b4 = B1.x, b5 = B1.y, b6 = B1.z;
        // accP[r] += C[s]*a[r+s];  accN[r] += C[s]*b[3+r-s]
        p0 = fmaf(C.x, a0, p0); n0 = fmaf(C.x, b3, n0);
        p0 = fmaf(C.y, a1, p0); n0 = fmaf(C.y, b2, n0);
        p0 = fmaf(C.z, a2, p0); n0 = fmaf(C.z, b1, n0);
        p0 = fmaf(C.w, a3, p0); n0 = fmaf(C.w, b0, n0);
        p1 = fmaf(C.x, a1, p1); n1 = fmaf(C.x, b4, n1);
        p1 = fmaf(C.y, a2, p1); n1 = fmaf(C.y, b3, n1);
        p1 = fmaf(C.z, a3, p1); n1 = fmaf(C.z, b2, n1);
        p1 = fmaf(C.w, a4, p1); n1 = fmaf(C.w, b1, n1);
        p2 = fmaf(C.x, a2, p2); n2 = fmaf(C.x, b5, n2);
        p2 = fmaf(C.y, a3, p2); n2 = fmaf(C.y, b4, n2);
        p2 = fmaf(C.z, a4, p2); n2 = fmaf(C.z, b3, n2);
        p2 = fmaf(C.w, a5, p2); n2 = fmaf(C.w, b2, n2);
        p3 = fmaf(C.x, a3, p3); n3 = fmaf(C.x, b6, n3);
        p3 = fmaf(C.y, a4, p3); n3 = fmaf(C.y, b5, n3);
        p3 = fmaf(C.z, a5, p3); n3 = fmaf(C.z, b4, n3);
        p3 = fmaf(C.w, a6, p3); n3 = fmaf(C.w, b3, n3);
        A0 = A1;                        // rolling reuse: A window +1, B window -1
        B1 = B0;
    }
    float acc0 = p0 - n0, acc1 = p1 - n1, acc2 = p2 - n2, acc3 = p3 - n3;

    // Lanes 0-15 of each warp absorb lanes 16-31 (same ly, j+1).
    acc0 += __shfl_down_sync(0xffffffffu, acc0, 16);
    acc1 += __shfl_down_sync(0xffffffffu, acc1, 16);
    acc2 += __shfl_down_sync(0xffffffffu, acc2, 16);
    acc3 += __shfl_down_sync(0xffffffffu, acc3, 16);

    const int lane = t & 31, w = t >> 5;
    if (lane < 16) {
        float4 v; v.x = acc0; v.y = acc1; v.z = acc2; v.w = acc3;
        ((float4*)(red2 + w * 68))[lane] = v;     // red2[w*68 + 4*ly + r]
    }
    __syncthreads();

    if (t < 64) {
        float s = 0.0f;
#pragma unroll
        for (int w2 = 0; w2 < 32; w2++) s += red2[w2 * 68 + t];
        Qs[t] = s;                       // ct2 already carries 2/L
    }
    __syncthreads();

    // 64 b x 64 m outputs, 4 per thread
#pragma unroll
    for (int r = 0; r < 4; r++) {
        int idx = r * 1024 + t;
        int b   = idx >> 6;
        int mm  = idx & 63;
        out[(size_t)b * L + 2 * (m0 + mm) + p] =
            fmaf(aS[b], Ps[mm], cS[b] * Qs[mm]);
    }
}

// ---------------------------------------------------------------------------
extern "C" void kernel_launch(void* const* d_in, const int* in_sizes, int n_in,
                              void* d_out, int out_size) {
    const float* u   = (const float*)d_in[0];  // (64, 8192)
    const float* ev  = (const float*)d_in[1];  // (32, 8192)
    const float* lam = (const float*)d_in[2];  // (32,)
    float* out = (float*)d_out;                // (64, 8192)

    kfused<<<NBLK, 1024>>>(u, ev, lam, out);
}